// round 13
// baseline (speedup 1.0000x reference)
#include <cuda_runtime.h>
#include <cuda_fp16.h>
#include <cstdint>
#include <cstddef>

#define S_SRC 2048
#define S_TGT 2048
#define BATCH 16
#define HDIM  256

typedef __half f16;

// ---------------------------------------------------------------------------
// Device-global scratch (allocation-free rule)
// ---------------------------------------------------------------------------
__device__ f16   g_dec_hi [(size_t)BATCH * S_TGT * HDIM];   // [b][t][h]
__device__ f16   g_dec_lo [(size_t)BATCH * S_TGT * HDIM];
__device__ f16   g_enc_hi [(size_t)BATCH * S_SRC * HDIM];   // [b][s][h]
__device__ f16   g_enc_lo [(size_t)BATCH * S_SRC * HDIM];
__device__ f16   g_encT_hi[(size_t)BATCH * HDIM  * S_SRC];  // [b][h][s]
__device__ float g_S      [(size_t)BATCH * S_TGT * S_SRC];  // fp32 scores
__device__ f16   g_P_hi   [(size_t)BATCH * S_TGT * S_SRC];  // probs fp16

__device__ __forceinline__ uint32_t smem_u32(const void* p) {
    uint32_t a;
    asm("{ .reg .u64 t; cvta.to.shared.u64 t, %1; cvt.u32.u64 %0, t; }" : "=r"(a) : "l"(p));
    return a;
}
__device__ __forceinline__ void cp_async16(uint32_t dst, const void* src) {
    asm volatile("cp.async.cg.shared.global [%0], [%1], 16;" :: "r"(dst), "l"(src));
}
#define CP_COMMIT() asm volatile("cp.async.commit_group;")
#define CP_WAIT(N)  asm volatile("cp.async.wait_group %0;" :: "n"(N))

__device__ __forceinline__ void ldsm4(unsigned* r, uint32_t a) {
    asm volatile("ldmatrix.sync.aligned.m8n8.x4.shared.b16 {%0,%1,%2,%3}, [%4];"
                 : "=r"(r[0]), "=r"(r[1]), "=r"(r[2]), "=r"(r[3]) : "r"(a));
}
__device__ __forceinline__ void mma_f16(float* d, const unsigned* a, const unsigned* b) {
    asm volatile(
        "mma.sync.aligned.m16n8k16.row.col.f32.f16.f16.f32 "
        "{%0,%1,%2,%3}, {%4,%5,%6,%7}, {%8,%9}, {%0,%1,%2,%3};\n"
        : "+f"(d[0]), "+f"(d[1]), "+f"(d[2]), "+f"(d[3])
        : "r"(a[0]), "r"(a[1]), "r"(a[2]), "r"(a[3]), "r"(b[0]), "r"(b[1]));
}
__device__ __forceinline__ void split_f16(float v, f16& hi, f16& lo) {
    hi = __float2half_rn(v);
    lo = __float2half_rn(v - __half2float(hi));
}

// ---------------------------------------------------------------------------
// Kernel 1: dec split fp16, batch-major, vectorized (4 h per thread)
// ---------------------------------------------------------------------------
__global__ void __launch_bounds__(256) prep_dec(const float* __restrict__ out_d) {
    int i = blockIdx.x * blockDim.x + threadIdx.x;
    int h4 = i & (HDIM / 4 - 1);
    int t  = (i >> 6) & (S_TGT - 1);
    int b  = i >> 17;
    float4 v = *(const float4*)(out_d + ((size_t)t * BATCH + b) * HDIM + h4 * 4);
    f16 h[4], l[4];
    split_f16(v.x, h[0], l[0]); split_f16(v.y, h[1], l[1]);
    split_f16(v.z, h[2], l[2]); split_f16(v.w, h[3], l[3]);
    size_t idx = ((size_t)b * S_TGT + t) * HDIM + h4 * 4;
    *(uint2*)(g_dec_hi + idx) = *(uint2*)h;
    *(uint2*)(g_dec_lo + idx) = *(uint2*)l;
}

// ---------------------------------------------------------------------------
// Kernel 2: enc = dir0+dir1 split fp16 (row-major hi/lo + transposed hi)
// float4 loads, packed uint32 transposed stores
// ---------------------------------------------------------------------------
__global__ void __launch_bounds__(256) transposeE_kernel(const float* __restrict__ out_e) {
    __shared__ uint32_t tile[32][33];   // tile[s_local][h_local] = hi bits
    int b  = blockIdx.z;
    int s0 = blockIdx.x * 32;
    int h0 = blockIdx.y * 32;
    int tid = threadIdx.x;

    // load: 256 threads, each handles one (row, float4) pair
    {
        int row = tid >> 3, f4 = tid & 7;
        size_t ebase = ((size_t)(s0 + row) * BATCH + b) * (2 * HDIM) + h0 + f4 * 4;
        float4 d0 = *(const float4*)(out_e + ebase);
        float4 d1 = *(const float4*)(out_e + ebase + HDIM);
        float e[4] = { d0.x + d1.x, d0.y + d1.y, d0.z + d1.z, d0.w + d1.w };
        f16 hi[4], lo[4];
        #pragma unroll
        for (int j = 0; j < 4; j++) {
            split_f16(e[j], hi[j], lo[j]);
            tile[row][f4 * 4 + j] = (uint32_t)__half_as_ushort(hi[j]);
        }
        size_t o = ((size_t)b * S_SRC + s0 + row) * HDIM + h0 + f4 * 4;
        *(uint2*)(g_enc_hi + o) = *(uint2*)hi;
        *(uint2*)(g_enc_lo + o) = *(uint2*)lo;
    }
    __syncthreads();

    // transposed store: 512 uint32 (2 s-values packed), 2 per thread
    #pragma unroll
    for (int j = 0; j < 2; j++) {
        int w = tid + j * 256;
        int h_local = w >> 4;
        int sp = w & 15;
        uint32_t v = tile[sp * 2][h_local] | (tile[sp * 2 + 1][h_local] << 16);
        size_t o = ((size_t)b * HDIM + h0 + h_local) * S_SRC + s0 + sp * 2;
        *(uint32_t*)(g_encT_hi + o) = v;
    }
}

// ---------------------------------------------------------------------------
// fp16 GEMM:  C[m][n] = sum_k A[m][k]*B[n][k]
// SPLIT: hh + lh + hl (all f32 acc), register-sequenced (peak ~104 live):
//   bh,ah -> hh | al -> lh | bl over bh -> hl
// !SPLIT: plain fp16 single product.
// Block 128x128, K-chunk KCH (32 QK / 64 PV), double-buffered cp.async,
// 8 warps (2m x 4n), __launch_bounds__(256,2) -> 2 CTAs/SM.
// ---------------------------------------------------------------------------
template<int KCH>
__device__ __forceinline__ void load_tile(uint32_t dst, const f16* __restrict__ g, int ldg) {
    const int ROWB = KCH * 2 + 16;
    const int NSEG = KCH / 8;            // 16B segments per row
    #pragma unroll
    for (int it = threadIdx.x; it < 128 * NSEG; it += 256) {
        int row = it / NSEG, seg = it % NSEG;
        cp_async16(dst + row * ROWB + seg * 16, g + (size_t)row * ldg + seg * 8);
    }
}

template<bool SPLIT, int KCH>
__global__ void __launch_bounds__(256, 2) gemm_f16(
    const f16* __restrict__ Ah, const f16* __restrict__ Al,
    const f16* __restrict__ Bh, const f16* __restrict__ Bl,
    float* __restrict__ C, int K,
    size_t strideA, size_t strideB, size_t strideC, int lda, int ldb, int ldc)
{
    extern __shared__ char smem[];
    uint32_t sbase = smem_u32(smem);
    const int ROWB = KCH * 2 + 16;
    const uint32_t ARR = 128 * ROWB;
    const int NARR = SPLIT ? 4 : 2;
    const uint32_t STG = NARR * ARR;
    const int NSTEP = KCH / 16;

    int b  = blockIdx.z;
    int bm = blockIdx.y, bn = blockIdx.x;
    const f16* Ahp = Ah + (size_t)b * strideA + (size_t)(bm * 128) * lda;
    const f16* Alp = SPLIT ? Al + (size_t)b * strideA + (size_t)(bm * 128) * lda : nullptr;
    const f16* Bhp = Bh + (size_t)b * strideB + (size_t)(bn * 128) * ldb;
    const f16* Blp = SPLIT ? Bl + (size_t)b * strideB + (size_t)(bn * 128) * ldb : nullptr;
    float*     Cb  = C  + (size_t)b * strideC;

    int tid  = threadIdx.x;
    int warp = tid >> 5, lane = tid & 31;
    int wm = warp >> 2, wn = warp & 3;
    int g  = lane >> 2, tg = lane & 3;

    int rA = (lane & 7) + ((lane >> 3) & 1) * 8;
    int cA = (lane >> 4) & 1;
    int rB = (lane & 7) + ((lane >> 4) & 1) * 8;
    int cB = (lane >> 3) & 1;
    uint32_t aOffH = 0 * ARR + (uint32_t)(wm * 64 + rA) * ROWB + cA * 16;
    uint32_t aOffL = 1 * ARR + (uint32_t)(wm * 64 + rA) * ROWB + cA * 16;
    uint32_t bOffH = (SPLIT ? 2 : 1) * ARR + (uint32_t)(wn * 32 + rB) * ROWB + cB * 16;
    uint32_t bOffL = 3 * ARR + (uint32_t)(wn * 32 + rB) * ROWB + cB * 16;

    float acc[4][4][4];
    #pragma unroll
    for (int i = 0; i < 4; i++)
        #pragma unroll
        for (int j = 0; j < 4; j++)
            #pragma unroll
            for (int k = 0; k < 4; k++) acc[i][j][k] = 0.f;

    int NCH = K / KCH;

    load_tile<KCH>(sbase + 0 * ARR, Ahp, lda);
    if (SPLIT) load_tile<KCH>(sbase + 1 * ARR, Alp, lda);
    load_tile<KCH>(sbase + (SPLIT ? 2 : 1) * ARR, Bhp, ldb);
    if (SPLIT) load_tile<KCH>(sbase + 3 * ARR, Blp, ldb);
    CP_COMMIT();

    for (int c = 0; c < NCH; c++) {
        if (c + 1 < NCH) {
            uint32_t st = sbase + ((c + 1) & 1) * STG;
            int k0 = (c + 1) * KCH;
            load_tile<KCH>(st + 0 * ARR, Ahp + k0, lda);
            if (SPLIT) load_tile<KCH>(st + 1 * ARR, Alp + k0, lda);
            load_tile<KCH>(st + (SPLIT ? 2 : 1) * ARR, Bhp + k0, ldb);
            if (SPLIT) load_tile<KCH>(st + 3 * ARR, Blp + k0, ldb);
            CP_COMMIT();
            CP_WAIT(1);
        } else {
            CP_WAIT(0);
        }
        __syncthreads();

        uint32_t sb = sbase + (c & 1) * STG;
        #pragma unroll
        for (int step = 0; step < NSTEP; step++) {
            unsigned bfr[2][4];
            ldsm4(bfr[0], sb + bOffH + step * 32);
            ldsm4(bfr[1], sb + bOffH + 16 * ROWB + step * 32);
            unsigned ah[4][4];
            #pragma unroll
            for (int mf = 0; mf < 4; mf++)
                ldsm4(ah[mf], sb + aOffH + mf * 16 * ROWB + step * 32);
            #pragma unroll
            for (int mf = 0; mf < 4; mf++)
                #pragma unroll
                for (int nf = 0; nf < 4; nf++) {
                    unsigned bb[2] = { bfr[nf >> 1][(nf & 1) * 2],
                                       bfr[nf >> 1][(nf & 1) * 2 + 1] };
                    mma_f16(acc[mf][nf], ah[mf], bb);
                }
            if (SPLIT) {
                unsigned al[4][4];
                #pragma unroll
                for (int mf = 0; mf < 4; mf++)
                    ldsm4(al[mf], sb + aOffL + mf * 16 * ROWB + step * 32);
                #pragma unroll
                for (int mf = 0; mf < 4; mf++)
                    #pragma unroll
                    for (int nf = 0; nf < 4; nf++) {
                        unsigned bb[2] = { bfr[nf >> 1][(nf & 1) * 2],
                                           bfr[nf >> 1][(nf & 1) * 2 + 1] };
                        mma_f16(acc[mf][nf], al[mf], bb);
                    }
                ldsm4(bfr[0], sb + bOffL + step * 32);
                ldsm4(bfr[1], sb + bOffL + 16 * ROWB + step * 32);
                #pragma unroll
                for (int mf = 0; mf < 4; mf++)
                    #pragma unroll
                    for (int nf = 0; nf < 4; nf++) {
                        unsigned bb[2] = { bfr[nf >> 1][(nf & 1) * 2],
                                           bfr[nf >> 1][(nf & 1) * 2 + 1] };
                        mma_f16(acc[mf][nf], ah[mf], bb);
                    }
            }
        }
        __syncthreads();
    }

    #pragma unroll
    for (int mf = 0; mf < 4; mf++) {
        #pragma unroll
        for (int nf = 0; nf < 4; nf++) {
            int r = bm * 128 + wm * 64 + mf * 16 + g;
            int c = bn * 128 + wn * 32 + nf * 8 + tg * 2;
            *(float2*)(Cb + (size_t)r * ldc + c)       = make_float2(acc[mf][nf][0], acc[mf][nf][1]);
            *(float2*)(Cb + (size_t)(r + 8) * ldc + c) = make_float2(acc[mf][nf][2], acc[mf][nf][3]);
        }
    }
}

#define GSMEM_QK (2 * 4 * (128 * (32 * 2 + 16)))   // 81920
#define GSMEM_PV (2 * 2 * (128 * (64 * 2 + 16)))   // 73728

// ---------------------------------------------------------------------------
// Kernel 4: softmax over s, reads fp32 S, writes fp16 P
// ---------------------------------------------------------------------------
__global__ void __launch_bounds__(256) softmax_kernel() {
    __shared__ float red[8];
    size_t row = blockIdx.x;
    const float* p = g_S + row * (size_t)S_SRC;
    int tid  = threadIdx.x;
    int lane = tid & 31, warp = tid >> 5;

    float4 v0 = ((const float4*)p)[tid];
    float4 v1 = ((const float4*)p)[tid + 256];

    float m = fmaxf(fmaxf(fmaxf(v0.x, v0.y), fmaxf(v0.z, v0.w)),
                    fmaxf(fmaxf(v1.x, v1.y), fmaxf(v1.z, v1.w)));
    #pragma unroll
    for (int o = 16; o; o >>= 1) m = fmaxf(m, __shfl_xor_sync(0xffffffffu, m, o));
    if (lane == 0) red[warp] = m;
    __syncthreads();
    float bm = red[0];
    #pragma unroll
    for (int i = 1; i < 8; i++) bm = fmaxf(bm, red[i]);
    __syncthreads();

    v0.x = __expf(v0.x - bm); v0.y = __expf(v0.y - bm);
    v0.z = __expf(v0.z - bm); v0.w = __expf(v0.w - bm);
    v1.x = __expf(v1.x - bm); v1.y = __expf(v1.y - bm);
    v1.z = __expf(v1.z - bm); v1.w = __expf(v1.w - bm);

    float s = v0.x + v0.y + v0.z + v0.w + v1.x + v1.y + v1.z + v1.w;
    #pragma unroll
    for (int o = 16; o; o >>= 1) s += __shfl_xor_sync(0xffffffffu, s, o);
    if (lane == 0) red[warp] = s;
    __syncthreads();
    float total = red[0];
    #pragma unroll
    for (int i = 1; i < 8; i++) total += red[i];
    float inv = 1.0f / total;

    f16* ph = g_P_hi + row * (size_t)S_SRC;
    f16 hb0[4] = { __float2half_rn(v0.x * inv), __float2half_rn(v0.y * inv),
                   __float2half_rn(v0.z * inv), __float2half_rn(v0.w * inv) };
    f16 hb1[4] = { __float2half_rn(v1.x * inv), __float2half_rn(v1.y * inv),
                   __float2half_rn(v1.z * inv), __float2half_rn(v1.w * inv) };
    *(uint2*)(ph + (size_t)tid * 4)         = *(uint2*)hb0;
    *(uint2*)(ph + (size_t)(256 + tid) * 4) = *(uint2*)hb1;
}

// ---------------------------------------------------------------------------
extern "C" void kernel_launch(void* const* d_in, const int* in_sizes, int n_in,
                              void* d_out, int out_size) {
    const float* out_e = (const float*)d_in[0];
    const float* out_d = (const float*)d_in[1];
    float* out = (float*)d_out;

    f16 *pDh, *pDl, *pEh, *pEl, *pTh, *pPh;
    float* pS;
    cudaGetSymbolAddress((void**)&pDh, g_dec_hi);
    cudaGetSymbolAddress((void**)&pDl, g_dec_lo);
    cudaGetSymbolAddress((void**)&pEh, g_enc_hi);
    cudaGetSymbolAddress((void**)&pEl, g_enc_lo);
    cudaGetSymbolAddress((void**)&pTh, g_encT_hi);
    cudaGetSymbolAddress((void**)&pPh, g_P_hi);
    cudaGetSymbolAddress((void**)&pS,  g_S);

    cudaFuncSetAttribute((void*)gemm_f16<true, 32>,
                         cudaFuncAttributeMaxDynamicSharedMemorySize, GSMEM_QK);
    cudaFuncSetAttribute((void*)gemm_f16<false, 64>,
                         cudaFuncAttributeMaxDynamicSharedMemorySize, GSMEM_PV);

    prep_dec<<<(BATCH * S_TGT * HDIM / 4) / 256, 256>>>(out_d);

    transposeE_kernel<<<dim3(S_SRC / 32, HDIM / 32, BATCH), 256>>>(out_e);

    // QK: S[b][t][s] = dec . enc  (M=2048, N=2048, K=256), 3-term split fp16
    gemm_f16<true, 32><<<dim3(S_SRC / 128, S_TGT / 128, BATCH), 256, GSMEM_QK>>>(
        pDh, pDl, pEh, pEl, pS, HDIM,
        (size_t)S_TGT * HDIM, (size_t)S_SRC * HDIM, (size_t)S_TGT * S_SRC,
        HDIM, HDIM, S_SRC);

    softmax_kernel<<<BATCH * S_TGT, 256>>>();

    // PV: out[t][b][h] = P . encT  (M=2048, N=256, K=2048), plain fp16, KCH=64
    gemm_f16<false, 64><<<dim3(HDIM / 128, S_TGT / 128, BATCH), 256, GSMEM_PV>>>(
        pPh, nullptr, pTh, nullptr, out, S_SRC,
        (size_t)S_TGT * S_SRC, (size_t)HDIM * S_SRC, (size_t)HDIM,
        S_SRC, S_SRC, BATCH * HDIM);
}

// round 14
// speedup vs baseline: 1.3847x; 1.3847x over previous
#include <cuda_runtime.h>
#include <cuda_fp16.h>
#include <cstdint>
#include <cstddef>

#define S_SRC 2048
#define S_TGT 2048
#define BATCH 16
#define HDIM  256

typedef __half f16;

// ---------------------------------------------------------------------------
// Device-global scratch (allocation-free rule)
// ---------------------------------------------------------------------------
__device__ f16   g_dec_hi [(size_t)BATCH * S_TGT * HDIM];   // [b][t][h]
__device__ f16   g_dec_lo [(size_t)BATCH * S_TGT * HDIM];
__device__ f16   g_enc_hi [(size_t)BATCH * S_SRC * HDIM];   // [b][s][h]
__device__ f16   g_enc_lo [(size_t)BATCH * S_SRC * HDIM];
__device__ f16   g_encT_hi[(size_t)BATCH * HDIM  * S_SRC];  // [b][h][s]
__device__ f16   g_S16    [(size_t)BATCH * S_TGT * S_SRC];  // s - tilemax, f16
__device__ float g_TM     [(size_t)BATCH * S_TGT * 16];     // per-(row,128-tile) max
__device__ f16   g_P_hi   [(size_t)BATCH * S_TGT * S_SRC];  // probs fp16

__device__ __forceinline__ uint32_t smem_u32(const void* p) {
    uint32_t a;
    asm("{ .reg .u64 t; cvta.to.shared.u64 t, %1; cvt.u32.u64 %0, t; }" : "=r"(a) : "l"(p));
    return a;
}
__device__ __forceinline__ void cp_async16(uint32_t dst, const void* src) {
    asm volatile("cp.async.cg.shared.global [%0], [%1], 16;" :: "r"(dst), "l"(src));
}
#define CP_COMMIT() asm volatile("cp.async.commit_group;")
#define CP_WAIT(N)  asm volatile("cp.async.wait_group %0;" :: "n"(N))

__device__ __forceinline__ void ldsm4(unsigned* r, uint32_t a) {
    asm volatile("ldmatrix.sync.aligned.m8n8.x4.shared.b16 {%0,%1,%2,%3}, [%4];"
                 : "=r"(r[0]), "=r"(r[1]), "=r"(r[2]), "=r"(r[3]) : "r"(a));
}
__device__ __forceinline__ void mma_f16(float* d, const unsigned* a, const unsigned* b) {
    asm volatile(
        "mma.sync.aligned.m16n8k16.row.col.f32.f16.f16.f32 "
        "{%0,%1,%2,%3}, {%4,%5,%6,%7}, {%8,%9}, {%0,%1,%2,%3};\n"
        : "+f"(d[0]), "+f"(d[1]), "+f"(d[2]), "+f"(d[3])
        : "r"(a[0]), "r"(a[1]), "r"(a[2]), "r"(a[3]), "r"(b[0]), "r"(b[1]));
}
__device__ __forceinline__ void split_f16(float v, f16& hi, f16& lo) {
    hi = __float2half_rn(v);
    lo = __float2half_rn(v - __half2float(hi));
}

// ---------------------------------------------------------------------------
// Kernel 1: dec split fp16, batch-major, vectorized (4 h per thread)
// ---------------------------------------------------------------------------
__global__ void __launch_bounds__(256) prep_dec(const float* __restrict__ out_d) {
    int i = blockIdx.x * blockDim.x + threadIdx.x;
    int h4 = i & (HDIM / 4 - 1);
    int t  = (i >> 6) & (S_TGT - 1);
    int b  = i >> 17;
    float4 v = *(const float4*)(out_d + ((size_t)t * BATCH + b) * HDIM + h4 * 4);
    f16 h[4], l[4];
    split_f16(v.x, h[0], l[0]); split_f16(v.y, h[1], l[1]);
    split_f16(v.z, h[2], l[2]); split_f16(v.w, h[3], l[3]);
    size_t idx = ((size_t)b * S_TGT + t) * HDIM + h4 * 4;
    *(uint2*)(g_dec_hi + idx) = *(uint2*)h;
    *(uint2*)(g_dec_lo + idx) = *(uint2*)l;
}

// ---------------------------------------------------------------------------
// Kernel 2: enc = dir0+dir1 split fp16 (row-major hi/lo + transposed hi)
// ---------------------------------------------------------------------------
__global__ void __launch_bounds__(256) transposeE_kernel(const float* __restrict__ out_e) {
    __shared__ uint32_t tile[32][33];
    int b  = blockIdx.z;
    int s0 = blockIdx.x * 32;
    int h0 = blockIdx.y * 32;
    int x = threadIdx.x;
    #pragma unroll
    for (int y = threadIdx.y; y < 32; y += 8) {
        size_t ebase = ((size_t)(s0 + y) * BATCH + b) * (2 * HDIM) + h0 + x;
        float e = out_e[ebase] + out_e[ebase + HDIM];
        f16 hi, lo;
        split_f16(e, hi, lo);
        tile[y][x] = (uint32_t)__half_as_ushort(hi);
        size_t o = ((size_t)b * S_SRC + s0 + y) * HDIM + h0 + x;
        g_enc_hi[o] = hi; g_enc_lo[o] = lo;
    }
    __syncthreads();
    #pragma unroll
    for (int y = threadIdx.y; y < 32; y += 8) {
        size_t o = ((size_t)b * HDIM + h0 + y) * S_SRC + s0 + x;
        g_encT_hi[o] = __ushort_as_half((unsigned short)tile[x][y]);
    }
}

// ---------------------------------------------------------------------------
// fp16 GEMM:  C[m][n] = sum_k A[m][k]*B[n][k]
// SPLIT (QK): hh + lh + hl (f32 acc), epilogue computes per-(row,tile) max,
//   writes g_TM and f16 relative scores to g_S16.
// !SPLIT (PV): plain fp16, fp32 epilogue to C.
// Block 128x128, K-chunk 32, double-buffered cp.async, 8 warps (2m x 4n),
// __launch_bounds__(256,2): 2 CTAs/SM.
// ---------------------------------------------------------------------------
#define ROWB   80
#define ARR    (128 * ROWB)

__device__ __forceinline__ void load_tile(uint32_t dst, const f16* __restrict__ g, int ldg) {
    #pragma unroll
    for (int it = threadIdx.x; it < 512; it += 256) {
        int row = it >> 2, seg = it & 3;
        cp_async16(dst + row * ROWB + seg * 16, g + (size_t)row * ldg + seg * 8);
    }
}

template<bool SPLIT>
__global__ void __launch_bounds__(256, 2) gemm_f16(
    const f16* __restrict__ Ah, const f16* __restrict__ Al,
    const f16* __restrict__ Bh, const f16* __restrict__ Bl,
    float* __restrict__ C, int K,
    size_t strideA, size_t strideB, size_t strideC, int lda, int ldb, int ldc)
{
    extern __shared__ char smem[];
    uint32_t sbase = smem_u32(smem);
    const int NARR = SPLIT ? 4 : 2;
    const uint32_t STG = NARR * ARR;

    int b  = blockIdx.z;
    int bm = blockIdx.y, bn = blockIdx.x;
    const f16* Ahp = Ah + (size_t)b * strideA + (size_t)(bm * 128) * lda;
    const f16* Alp = SPLIT ? Al + (size_t)b * strideA + (size_t)(bm * 128) * lda : nullptr;
    const f16* Bhp = Bh + (size_t)b * strideB + (size_t)(bn * 128) * ldb;
    const f16* Blp = SPLIT ? Bl + (size_t)b * strideB + (size_t)(bn * 128) * ldb : nullptr;
    float*     Cb  = C  + (size_t)b * strideC;

    int tid  = threadIdx.x;
    int warp = tid >> 5, lane = tid & 31;
    int wm = warp >> 2, wn = warp & 3;
    int g  = lane >> 2, tg = lane & 3;

    int rA = (lane & 7) + ((lane >> 3) & 1) * 8;
    int cA = (lane >> 4) & 1;
    int rB = (lane & 7) + ((lane >> 4) & 1) * 8;
    int cB = (lane >> 3) & 1;
    uint32_t aOffH = 0 * ARR + (uint32_t)(wm * 64 + rA) * ROWB + cA * 16;
    uint32_t aOffL = 1 * ARR + (uint32_t)(wm * 64 + rA) * ROWB + cA * 16;
    uint32_t bOffH = (SPLIT ? 2 : 1) * ARR + (uint32_t)(wn * 32 + rB) * ROWB + cB * 16;
    uint32_t bOffL = 3 * ARR + (uint32_t)(wn * 32 + rB) * ROWB + cB * 16;

    float acc[4][4][4];
    #pragma unroll
    for (int i = 0; i < 4; i++)
        #pragma unroll
        for (int j = 0; j < 4; j++)
            #pragma unroll
            for (int k = 0; k < 4; k++) acc[i][j][k] = 0.f;

    int NCH = K >> 5;

    load_tile(sbase + 0 * ARR, Ahp, lda);
    if (SPLIT) load_tile(sbase + 1 * ARR, Alp, lda);
    load_tile(sbase + (SPLIT ? 2 : 1) * ARR, Bhp, ldb);
    if (SPLIT) load_tile(sbase + 3 * ARR, Blp, ldb);
    CP_COMMIT();

    for (int c = 0; c < NCH; c++) {
        if (c + 1 < NCH) {
            uint32_t st = sbase + ((c + 1) & 1) * STG;
            int k0 = (c + 1) * 32;
            load_tile(st + 0 * ARR, Ahp + k0, lda);
            if (SPLIT) load_tile(st + 1 * ARR, Alp + k0, lda);
            load_tile(st + (SPLIT ? 2 : 1) * ARR, Bhp + k0, ldb);
            if (SPLIT) load_tile(st + 3 * ARR, Blp + k0, ldb);
            CP_COMMIT();
            CP_WAIT(1);
        } else {
            CP_WAIT(0);
        }
        __syncthreads();

        uint32_t sb = sbase + (c & 1) * STG;
        #pragma unroll
        for (int step = 0; step < 2; step++) {
            unsigned bfr[2][4];
            ldsm4(bfr[0], sb + bOffH + step * 32);
            ldsm4(bfr[1], sb + bOffH + 16 * ROWB + step * 32);
            unsigned ah[4][4];
            #pragma unroll
            for (int mf = 0; mf < 4; mf++)
                ldsm4(ah[mf], sb + aOffH + mf * 16 * ROWB + step * 32);
            #pragma unroll
            for (int mf = 0; mf < 4; mf++)
                #pragma unroll
                for (int nf = 0; nf < 4; nf++) {
                    unsigned bb[2] = { bfr[nf >> 1][(nf & 1) * 2],
                                       bfr[nf >> 1][(nf & 1) * 2 + 1] };
                    mma_f16(acc[mf][nf], ah[mf], bb);
                }
            if (SPLIT) {
                unsigned al[4][4];
                #pragma unroll
                for (int mf = 0; mf < 4; mf++)
                    ldsm4(al[mf], sb + aOffL + mf * 16 * ROWB + step * 32);
                #pragma unroll
                for (int mf = 0; mf < 4; mf++)
                    #pragma unroll
                    for (int nf = 0; nf < 4; nf++) {
                        unsigned bb[2] = { bfr[nf >> 1][(nf & 1) * 2],
                                           bfr[nf >> 1][(nf & 1) * 2 + 1] };
                        mma_f16(acc[mf][nf], al[mf], bb);
                    }
                ldsm4(bfr[0], sb + bOffL + step * 32);
                ldsm4(bfr[1], sb + bOffL + 16 * ROWB + step * 32);
                #pragma unroll
                for (int mf = 0; mf < 4; mf++)
                    #pragma unroll
                    for (int nf = 0; nf < 4; nf++) {
                        unsigned bb[2] = { bfr[nf >> 1][(nf & 1) * 2],
                                           bfr[nf >> 1][(nf & 1) * 2 + 1] };
                        mma_f16(acc[mf][nf], ah[mf], bb);
                    }
            }
        }
        __syncthreads();
    }

    if (SPLIT) {
        // -------- QK epilogue: per-(row, 128-tile) max + f16 relative scores
        float* red = (float*)smem;   // 512 floats (buffers no longer needed)
        #pragma unroll
        for (int mf = 0; mf < 4; mf++)
            #pragma unroll
            for (int hf = 0; hf < 2; hf++) {
                float v = -1e30f;
                #pragma unroll
                for (int nf = 0; nf < 4; nf++)
                    v = fmaxf(v, fmaxf(acc[mf][nf][hf * 2], acc[mf][nf][hf * 2 + 1]));
                v = fmaxf(v, __shfl_xor_sync(0xffffffffu, v, 1));
                v = fmaxf(v, __shfl_xor_sync(0xffffffffu, v, 2));
                if (tg == 0) red[wn * 128 + wm * 64 + mf * 16 + hf * 8 + g] = v;
            }
        __syncthreads();

        float mr[4][2];
        int t0 = bm * 128;
        #pragma unroll
        for (int mf = 0; mf < 4; mf++)
            #pragma unroll
            for (int hf = 0; hf < 2; hf++) {
                int rl = wm * 64 + mf * 16 + hf * 8 + g;
                float v = fmaxf(fmaxf(red[rl], red[128 + rl]),
                                fmaxf(red[256 + rl], red[384 + rl]));
                mr[mf][hf] = v;
                if (wn == 0 && tg == 0)
                    g_TM[((size_t)b * S_TGT + t0 + rl) * 16 + bn] = v;
            }

        #pragma unroll
        for (int mf = 0; mf < 4; mf++) {
            int r = t0 + wm * 64 + mf * 16 + g;
            #pragma unroll
            for (int nf = 0; nf < 4; nf++) {
                int cc = bn * 128 + wn * 32 + nf * 8 + tg * 2;
                __half2 v0 = __floats2half2_rn(acc[mf][nf][0] - mr[mf][0],
                                               acc[mf][nf][1] - mr[mf][0]);
                __half2 v1 = __floats2half2_rn(acc[mf][nf][2] - mr[mf][1],
                                               acc[mf][nf][3] - mr[mf][1]);
                *(__half2*)(g_S16 + ((size_t)b * S_TGT + r) * S_SRC + cc)     = v0;
                *(__half2*)(g_S16 + ((size_t)b * S_TGT + r + 8) * S_SRC + cc) = v1;
            }
        }
    } else {
        // -------- PV epilogue: fp32 to C
        #pragma unroll
        for (int mf = 0; mf < 4; mf++) {
            #pragma unroll
            for (int nf = 0; nf < 4; nf++) {
                int r = bm * 128 + wm * 64 + mf * 16 + g;
                int cc = bn * 128 + wn * 32 + nf * 8 + tg * 2;
                *(float2*)(Cb + (size_t)r * ldc + cc)       = make_float2(acc[mf][nf][0], acc[mf][nf][1]);
                *(float2*)(Cb + (size_t)(r + 8) * ldc + cc) = make_float2(acc[mf][nf][2], acc[mf][nf][3]);
            }
        }
    }
}

#define GSMEM3 (2 * 4 * ARR)
#define GSMEM1 (2 * 2 * ARR)

// ---------------------------------------------------------------------------
// Kernel 4: softmax over s — reads f16 relative scores + tile maxes, writes P
// thread handles 8 contiguous cols (one uint4), all within one 128-col tile
// ---------------------------------------------------------------------------
__global__ void __launch_bounds__(256) softmax_kernel() {
    __shared__ float red[8];
    size_t row = blockIdx.x;
    const f16* ps = g_S16 + row * (size_t)S_SRC;
    int tid  = threadIdx.x;
    int lane = tid & 31, warp = tid >> 5;

    float tm = g_TM[row * 16 + (tid >> 4)];

    // block max of tile maxes -> global row max m
    float m = tm;
    #pragma unroll
    for (int o = 16; o; o >>= 1) m = fmaxf(m, __shfl_xor_sync(0xffffffffu, m, o));
    if (lane == 0) red[warp] = m;
    __syncthreads();
    m = red[0];
    #pragma unroll
    for (int i = 1; i < 8; i++) m = fmaxf(m, red[i]);
    __syncthreads();

    float bias = tm - m;   // <= 0

    uint4 raw = ((const uint4*)ps)[tid];
    __half2* hp = (__half2*)&raw;
    float p[8];
    float s = 0.f;
    #pragma unroll
    for (int j = 0; j < 4; j++) {
        float2 v = __half22float2(hp[j]);
        p[j * 2]     = __expf(v.x + bias);
        p[j * 2 + 1] = __expf(v.y + bias);
        s += p[j * 2] + p[j * 2 + 1];
    }
    #pragma unroll
    for (int o = 16; o; o >>= 1) s += __shfl_xor_sync(0xffffffffu, s, o);
    if (lane == 0) red[warp] = s;
    __syncthreads();
    float total = red[0];
    #pragma unroll
    for (int i = 1; i < 8; i++) total += red[i];
    float inv = 1.0f / total;

    uint4 outp;
    __half2* op = (__half2*)&outp;
    #pragma unroll
    for (int j = 0; j < 4; j++)
        op[j] = __floats2half2_rn(p[j * 2] * inv, p[j * 2 + 1] * inv);
    ((uint4*)(g_P_hi + row * (size_t)S_SRC))[tid] = outp;
}

// ---------------------------------------------------------------------------
extern "C" void kernel_launch(void* const* d_in, const int* in_sizes, int n_in,
                              void* d_out, int out_size) {
    const float* out_e = (const float*)d_in[0];
    const float* out_d = (const float*)d_in[1];
    float* out = (float*)d_out;

    f16 *pDh, *pDl, *pEh, *pEl, *pTh, *pPh;
    cudaGetSymbolAddress((void**)&pDh, g_dec_hi);
    cudaGetSymbolAddress((void**)&pDl, g_dec_lo);
    cudaGetSymbolAddress((void**)&pEh, g_enc_hi);
    cudaGetSymbolAddress((void**)&pEl, g_enc_lo);
    cudaGetSymbolAddress((void**)&pTh, g_encT_hi);
    cudaGetSymbolAddress((void**)&pPh, g_P_hi);

    cudaFuncSetAttribute(gemm_f16<true>,  cudaFuncAttributeMaxDynamicSharedMemorySize, GSMEM3);
    cudaFuncSetAttribute(gemm_f16<false>, cudaFuncAttributeMaxDynamicSharedMemorySize, GSMEM1);

    prep_dec<<<(BATCH * S_TGT * HDIM / 4) / 256, 256>>>(out_d);

    transposeE_kernel<<<dim3(S_SRC / 32, HDIM / 32, BATCH), dim3(32, 8)>>>(out_e);

    // QK: relative-f16 scores + tile maxes (M=2048, N=2048, K=256), 3-term split
    gemm_f16<true><<<dim3(S_SRC / 128, S_TGT / 128, BATCH), 256, GSMEM3>>>(
        pDh, pDl, pEh, pEl, nullptr, HDIM,
        (size_t)S_TGT * HDIM, (size_t)S_SRC * HDIM, 0, HDIM, HDIM, 0);

    softmax_kernel<<<BATCH * S_TGT, 256>>>();

    // PV: out[t][b][h] = P . encT  (M=2048, N=256, K=2048), plain fp16
    gemm_f16<false><<<dim3(HDIM / 128, S_TGT / 128, BATCH), 256, GSMEM1>>>(
        pPh, nullptr, pTh, nullptr, out, S_SRC,
        (size_t)S_TGT * S_SRC, (size_t)HDIM * S_SRC, (size_t)HDIM,
        S_SRC, S_SRC, BATCH * HDIM);
}

// round 16
// speedup vs baseline: 1.4157x; 1.0224x over previous
#include <cuda_runtime.h>
#include <cuda_fp16.h>
#include <cstdint>
#include <cstddef>

#define S_SRC 2048
#define S_TGT 2048
#define BATCH 16
#define HDIM  256

typedef __half f16;

// ---------------------------------------------------------------------------
// Device-global scratch (allocation-free rule)
// ---------------------------------------------------------------------------
__device__ f16   g_dec_hi [(size_t)BATCH * S_TGT * HDIM];   // [b][t][h]
__device__ f16   g_dec_lo [(size_t)BATCH * S_TGT * HDIM];
__device__ f16   g_enc_hi [(size_t)BATCH * S_SRC * HDIM];   // [b][s][h]
__device__ f16   g_enc_lo [(size_t)BATCH * S_SRC * HDIM];
__device__ f16   g_encT_hi[(size_t)BATCH * HDIM  * S_SRC];  // [b][h][s]
__device__ float g_S      [(size_t)BATCH * S_TGT * S_SRC];  // fp32 scores
__device__ f16   g_P_hi   [(size_t)BATCH * S_TGT * S_SRC];  // probs fp16

__device__ __forceinline__ uint32_t smem_u32(const void* p) {
    uint32_t a;
    asm("{ .reg .u64 t; cvta.to.shared.u64 t, %1; cvt.u32.u64 %0, t; }" : "=r"(a) : "l"(p));
    return a;
}
__device__ __forceinline__ void cp_async16(uint32_t dst, const void* src) {
    asm volatile("cp.async.cg.shared.global [%0], [%1], 16;" :: "r"(dst), "l"(src));
}
#define CP_COMMIT() asm volatile("cp.async.commit_group;")
#define CP_WAIT(N)  asm volatile("cp.async.wait_group %0;" :: "n"(N))
__device__ __forceinline__ void cp_wait_dyn(int n) {
    switch (n) {
        case 0: CP_WAIT(0); break;
        case 1: CP_WAIT(1); break;
        case 2: CP_WAIT(2); break;
        default: CP_WAIT(3); break;
    }
}

__device__ __forceinline__ void ldsm4(unsigned* r, uint32_t a) {
    asm volatile("ldmatrix.sync.aligned.m8n8.x4.shared.b16 {%0,%1,%2,%3}, [%4];"
                 : "=r"(r[0]), "=r"(r[1]), "=r"(r[2]), "=r"(r[3]) : "r"(a));
}
__device__ __forceinline__ void mma_f16(float* d, const unsigned* a, const unsigned* b) {
    asm volatile(
        "mma.sync.aligned.m16n8k16.row.col.f32.f16.f16.f32 "
        "{%0,%1,%2,%3}, {%4,%5,%6,%7}, {%8,%9}, {%0,%1,%2,%3};\n"
        : "+f"(d[0]), "+f"(d[1]), "+f"(d[2]), "+f"(d[3])
        : "r"(a[0]), "r"(a[1]), "r"(a[2]), "r"(a[3]), "r"(b[0]), "r"(b[1]));
}
__device__ __forceinline__ void split_f16(float v, f16& hi, f16& lo) {
    hi = __float2half_rn(v);
    lo = __float2half_rn(v - __half2float(hi));
}

// ---------------------------------------------------------------------------
// Kernel 1: dec split fp16, batch-major, vectorized (4 h per thread)
// ---------------------------------------------------------------------------
__global__ void __launch_bounds__(256) prep_dec(const float* __restrict__ out_d) {
    int i = blockIdx.x * blockDim.x + threadIdx.x;
    int h4 = i & (HDIM / 4 - 1);
    int t  = (i >> 6) & (S_TGT - 1);
    int b  = i >> 17;
    float4 v = *(const float4*)(out_d + ((size_t)t * BATCH + b) * HDIM + h4 * 4);
    f16 h[4], l[4];
    split_f16(v.x, h[0], l[0]); split_f16(v.y, h[1], l[1]);
    split_f16(v.z, h[2], l[2]); split_f16(v.w, h[3], l[3]);
    size_t idx = ((size_t)b * S_TGT + t) * HDIM + h4 * 4;
    *(uint2*)(g_dec_hi + idx) = *(uint2*)h;
    *(uint2*)(g_dec_lo + idx) = *(uint2*)l;
}

// ---------------------------------------------------------------------------
// Kernel 2: enc = dir0+dir1 split fp16 (row-major hi/lo + transposed hi)
// ---------------------------------------------------------------------------
__global__ void __launch_bounds__(256) transposeE_kernel(const float* __restrict__ out_e) {
    __shared__ uint32_t tile[32][33];
    int b  = blockIdx.z;
    int s0 = blockIdx.x * 32;
    int h0 = blockIdx.y * 32;
    int x = threadIdx.x;
    #pragma unroll
    for (int y = threadIdx.y; y < 32; y += 8) {
        size_t ebase = ((size_t)(s0 + y) * BATCH + b) * (2 * HDIM) + h0 + x;
        float e = out_e[ebase] + out_e[ebase + HDIM];
        f16 hi, lo;
        split_f16(e, hi, lo);
        tile[y][x] = (uint32_t)__half_as_ushort(hi);
        size_t o = ((size_t)b * S_SRC + s0 + y) * HDIM + h0 + x;
        g_enc_hi[o] = hi; g_enc_lo[o] = lo;
    }
    __syncthreads();
    #pragma unroll
    for (int y = threadIdx.y; y < 32; y += 8) {
        size_t o = ((size_t)b * HDIM + h0 + y) * S_SRC + s0 + x;
        g_encT_hi[o] = __ushort_as_half((unsigned short)tile[x][y]);
    }
}

// ---------------------------------------------------------------------------
// fp16 GEMM:  C[m][n] = sum_k A[m][k]*B[n][k]
// SPLIT (QK): 3-term  hh + lh + hl (f32 acc), register-sequenced.
// !SPLIT (PV): plain fp16 single product.
// Block 128x128, K-chunk 32, NSTG-stage cp.async ring, 8 warps (2m x 4n),
// __launch_bounds__(256,2): 2 CTAs/SM.
// ---------------------------------------------------------------------------
#define ROWB   80
#define ARR    (128 * ROWB)

__device__ __forceinline__ void load_tile(uint32_t dst, const f16* __restrict__ g, int ldg) {
    #pragma unroll
    for (int it = threadIdx.x; it < 512; it += 256) {
        int row = it >> 2, seg = it & 3;
        cp_async16(dst + row * ROWB + seg * 16, g + (size_t)row * ldg + seg * 8);
    }
}

template<bool SPLIT, int NSTG>
__global__ void __launch_bounds__(256, 2) gemm_f16(
    const f16* __restrict__ Ah, const f16* __restrict__ Al,
    const f16* __restrict__ Bh, const f16* __restrict__ Bl,
    float* __restrict__ C, int K,
    size_t strideA, size_t strideB, size_t strideC, int lda, int ldb, int ldc)
{
    static_assert((NSTG & (NSTG - 1)) == 0, "stages power of 2");
    extern __shared__ char smem[];
    uint32_t sbase = smem_u32(smem);
    const int NARR = SPLIT ? 4 : 2;
    const uint32_t STG = NARR * ARR;

    int b  = blockIdx.z;
    int bm = blockIdx.y, bn = blockIdx.x;
    const f16* Ahp = Ah + (size_t)b * strideA + (size_t)(bm * 128) * lda;
    const f16* Alp = SPLIT ? Al + (size_t)b * strideA + (size_t)(bm * 128) * lda : nullptr;
    const f16* Bhp = Bh + (size_t)b * strideB + (size_t)(bn * 128) * ldb;
    const f16* Blp = SPLIT ? Bl + (size_t)b * strideB + (size_t)(bn * 128) * ldb : nullptr;
    float*     Cb  = C  + (size_t)b * strideC;

    int tid  = threadIdx.x;
    int warp = tid >> 5, lane = tid & 31;
    int wm = warp >> 2, wn = warp & 3;
    int g  = lane >> 2, tg = lane & 3;

    int rA = (lane & 7) + ((lane >> 3) & 1) * 8;
    int cA = (lane >> 4) & 1;
    int rB = (lane & 7) + ((lane >> 4) & 1) * 8;
    int cB = (lane >> 3) & 1;
    uint32_t aOffH = 0 * ARR + (uint32_t)(wm * 64 + rA) * ROWB + cA * 16;
    uint32_t aOffL = 1 * ARR + (uint32_t)(wm * 64 + rA) * ROWB + cA * 16;
    uint32_t bOffH = (SPLIT ? 2 : 1) * ARR + (uint32_t)(wn * 32 + rB) * ROWB + cB * 16;
    uint32_t bOffL = 3 * ARR + (uint32_t)(wn * 32 + rB) * ROWB + cB * 16;

    float acc[4][4][4];
    #pragma unroll
    for (int i = 0; i < 4; i++)
        #pragma unroll
        for (int j = 0; j < 4; j++)
            #pragma unroll
            for (int k = 0; k < 4; k++) acc[i][j][k] = 0.f;

    int NCH = K >> 5;

    // prologue: load chunks 0..NSTG-2
    #pragma unroll
    for (int c0 = 0; c0 < NSTG - 1; c0++) {
        if (c0 < NCH) {
            uint32_t st = sbase + c0 * STG;
            int k0 = c0 * 32;
            load_tile(st + 0 * ARR, Ahp + k0, lda);
            if (SPLIT) load_tile(st + 1 * ARR, Alp + k0, lda);
            load_tile(st + (SPLIT ? 2 : 1) * ARR, Bhp + k0, ldb);
            if (SPLIT) load_tile(st + 3 * ARR, Blp + k0, ldb);
            CP_COMMIT();
        }
    }

    for (int c = 0; c < NCH; c++) {
        if (c + NSTG - 1 < NCH) {
            uint32_t st = sbase + ((c + NSTG - 1) & (NSTG - 1)) * STG;
            int k0 = (c + NSTG - 1) * 32;
            load_tile(st + 0 * ARR, Ahp + k0, lda);
            if (SPLIT) load_tile(st + 1 * ARR, Alp + k0, lda);
            load_tile(st + (SPLIT ? 2 : 1) * ARR, Bhp + k0, ldb);
            if (SPLIT) load_tile(st + 3 * ARR, Blp + k0, ldb);
            CP_COMMIT();
        }
        int rem = NCH - 1 - c;
        cp_wait_dyn(rem < NSTG - 1 ? rem : NSTG - 1);
        __syncthreads();

        uint32_t sb = sbase + (c & (NSTG - 1)) * STG;
        #pragma unroll
        for (int step = 0; step < 2; step++) {
            unsigned bfr[2][4];
            ldsm4(bfr[0], sb + bOffH + step * 32);
            ldsm4(bfr[1], sb + bOffH + 16 * ROWB + step * 32);
            unsigned ah[4][4];
            #pragma unroll
            for (int mf = 0; mf < 4; mf++)
                ldsm4(ah[mf], sb + aOffH + mf * 16 * ROWB + step * 32);
            #pragma unroll
            for (int mf = 0; mf < 4; mf++)
                #pragma unroll
                for (int nf = 0; nf < 4; nf++) {
                    unsigned bb[2] = { bfr[nf >> 1][(nf & 1) * 2],
                                       bfr[nf >> 1][(nf & 1) * 2 + 1] };
                    mma_f16(acc[mf][nf], ah[mf], bb);              // hh
                }
            if (SPLIT) {
                unsigned al[4][4];
                #pragma unroll
                for (int mf = 0; mf < 4; mf++)
                    ldsm4(al[mf], sb + aOffL + mf * 16 * ROWB + step * 32);
                #pragma unroll
                for (int mf = 0; mf < 4; mf++)
                    #pragma unroll
                    for (int nf = 0; nf < 4; nf++) {
                        unsigned bb[2] = { bfr[nf >> 1][(nf & 1) * 2],
                                           bfr[nf >> 1][(nf & 1) * 2 + 1] };
                        mma_f16(acc[mf][nf], al[mf], bb);          // lh
                    }
                ldsm4(bfr[0], sb + bOffL + step * 32);
                ldsm4(bfr[1], sb + bOffL + 16 * ROWB + step * 32);
                #pragma unroll
                for (int mf = 0; mf < 4; mf++)
                    #pragma unroll
                    for (int nf = 0; nf < 4; nf++) {
                        unsigned bb[2] = { bfr[nf >> 1][(nf & 1) * 2],
                                           bfr[nf >> 1][(nf & 1) * 2 + 1] };
                        mma_f16(acc[mf][nf], ah[mf], bb);          // hl
                    }
            }
        }
        __syncthreads();
    }

    #pragma unroll
    for (int mf = 0; mf < 4; mf++) {
        #pragma unroll
        for (int nf = 0; nf < 4; nf++) {
            int r = bm * 128 + wm * 64 + mf * 16 + g;
            int c = bn * 128 + wn * 32 + nf * 8 + tg * 2;
            *(float2*)(Cb + (size_t)r * ldc + c)       = make_float2(acc[mf][nf][0], acc[mf][nf][1]);
            *(float2*)(Cb + (size_t)(r + 8) * ldc + c) = make_float2(acc[mf][nf][2], acc[mf][nf][3]);
        }
    }
}

#define GSMEM_QK (2 * 4 * ARR)   // 81920 : 2 stages x 4 arrays
#define GSMEM_PV (4 * 2 * ARR)   // 81920 : 4 stages x 2 arrays

// ---------------------------------------------------------------------------
// Kernel 4: softmax over s, reads fp32 S, writes fp16 P
// ---------------------------------------------------------------------------
__global__ void __launch_bounds__(256) softmax_kernel() {
    __shared__ float red[8];
    size_t row = blockIdx.x;
    const float* p = g_S + row * (size_t)S_SRC;
    int tid  = threadIdx.x;
    int lane = tid & 31, warp = tid >> 5;

    float4 v0 = ((const float4*)p)[tid];
    float4 v1 = ((const float4*)p)[tid + 256];

    float m = fmaxf(fmaxf(fmaxf(v0.x, v0.y), fmaxf(v0.z, v0.w)),
                    fmaxf(fmaxf(v1.x, v1.y), fmaxf(v1.z, v1.w)));
    #pragma unroll
    for (int o = 16; o; o >>= 1) m = fmaxf(m, __shfl_xor_sync(0xffffffffu, m, o));
    if (lane == 0) red[warp] = m;
    __syncthreads();
    float bm = red[0];
    #pragma unroll
    for (int i = 1; i < 8; i++) bm = fmaxf(bm, red[i]);
    __syncthreads();

    v0.x = __expf(v0.x - bm); v0.y = __expf(v0.y - bm);
    v0.z = __expf(v0.z - bm); v0.w = __expf(v0.w - bm);
    v1.x = __expf(v1.x - bm); v1.y = __expf(v1.y - bm);
    v1.z = __expf(v1.z - bm); v1.w = __expf(v1.w - bm);

    float s = v0.x + v0.y + v0.z + v0.w + v1.x + v1.y + v1.z + v1.w;
    #pragma unroll
    for (int o = 16; o; o >>= 1) s += __shfl_xor_sync(0xffffffffu, s, o);
    if (lane == 0) red[warp] = s;
    __syncthreads();
    float total = red[0];
    #pragma unroll
    for (int i = 1; i < 8; i++) total += red[i];
    float inv = 1.0f / total;

    f16* ph = g_P_hi + row * (size_t)S_SRC;
    f16 hb0[4] = { __float2half_rn(v0.x * inv), __float2half_rn(v0.y * inv),
                   __float2half_rn(v0.z * inv), __float2half_rn(v0.w * inv) };
    f16 hb1[4] = { __float2half_rn(v1.x * inv), __float2half_rn(v1.y * inv),
                   __float2half_rn(v1.z * inv), __float2half_rn(v1.w * inv) };
    *(uint2*)(ph + (size_t)tid * 4)         = *(uint2*)hb0;
    *(uint2*)(ph + (size_t)(256 + tid) * 4) = *(uint2*)hb1;
}

// ---------------------------------------------------------------------------
extern "C" void kernel_launch(void* const* d_in, const int* in_sizes, int n_in,
                              void* d_out, int out_size) {
    const float* out_e = (const float*)d_in[0];
    const float* out_d = (const float*)d_in[1];
    float* out = (float*)d_out;

    f16 *pDh, *pDl, *pEh, *pEl, *pTh, *pPh;
    float* pS;
    cudaGetSymbolAddress((void**)&pDh, g_dec_hi);
    cudaGetSymbolAddress((void**)&pDl, g_dec_lo);
    cudaGetSymbolAddress((void**)&pEh, g_enc_hi);
    cudaGetSymbolAddress((void**)&pEl, g_enc_lo);
    cudaGetSymbolAddress((void**)&pTh, g_encT_hi);
    cudaGetSymbolAddress((void**)&pPh, g_P_hi);
    cudaGetSymbolAddress((void**)&pS,  g_S);

    cudaFuncSetAttribute((void*)gemm_f16<true, 2>,
                         cudaFuncAttributeMaxDynamicSharedMemorySize, GSMEM_QK);
    cudaFuncSetAttribute((void*)gemm_f16<false, 4>,
                         cudaFuncAttributeMaxDynamicSharedMemorySize, GSMEM_PV);

    prep_dec<<<(BATCH * S_TGT * HDIM / 4) / 256, 256>>>(out_d);

    transposeE_kernel<<<dim3(S_SRC / 32, HDIM / 32, BATCH), dim3(32, 8)>>>(out_e);

    // QK: S[b][t][s] = dec . enc  (M=2048, N=2048, K=256), 3-term split fp16
    gemm_f16<true, 2><<<dim3(S_SRC / 128, S_TGT / 128, BATCH), 256, GSMEM_QK>>>(
        pDh, pDl, pEh, pEl, pS, HDIM,
        (size_t)S_TGT * HDIM, (size_t)S_SRC * HDIM, (size_t)S_TGT * S_SRC,
        HDIM, HDIM, S_SRC);

    softmax_kernel<<<BATCH * S_TGT, 256>>>();

    // PV: out[t][b][h] = P . encT  (M=2048, N=256, K=2048), plain fp16, 4-stage
    gemm_f16<false, 4><<<dim3(HDIM / 128, S_TGT / 128, BATCH), 256, GSMEM_PV>>>(
        pPh, nullptr, pTh, nullptr, out, S_SRC,
        (size_t)S_TGT * S_SRC, (size_t)HDIM * S_SRC, (size_t)HDIM,
        S_SRC, S_SRC, BATCH * HDIM);
}